// round 1
// baseline (speedup 1.0000x reference)
#include <cuda_runtime.h>
#include <cuda_bf16.h>
#include <math.h>

#define N_IMG 512
#define N_ANGLES 180
#define PW 514               // padded image dimension (1-pixel zero border)
#define C_HALF 255.5f        // (N-1)/2

// Scratch: padded image and padded transposed image (zero border).
__device__ float g_P [PW * PW];
__device__ float g_PT[PW * PW];

// Fill padded + padded-transposed copies. Border rows/cols are zero.
__global__ void prep_kernel(const float* __restrict__ img) {
    int idx = blockIdx.x * blockDim.x + threadIdx.x;
    if (idx >= PW * PW) return;
    int r = idx / PW;
    int cc = idx - r * PW;
    float v = 0.f, vt = 0.f;
    if (r >= 1 && r <= N_IMG && cc >= 1 && cc <= N_IMG) {
        v  = img[(r - 1) * N_IMG + (cc - 1)];
        vt = img[(cc - 1) * N_IMG + (r - 1)];
    }
    g_P [idx] = v;
    g_PT[idx] = vt;
}

__device__ __forceinline__ int clampi(int v, int lo, int hi) {
    return min(max(v, lo), hi);
}

// One thread = one (detector j, angle a) pair; walks the line i = 0..511.
__global__ void __launch_bounds__(128) radon_kernel(const int* __restrict__ angles,
                                                    float* __restrict__ out) {
    const int a = blockIdx.y;
    const int j = blockIdx.x * blockDim.x + threadIdx.x;

    const float t  = (float)angles[a] * (float)(3.14159265358979323846 / 180.0);
    const float co = cosf(t);
    const float si = sinf(t);
    const float x  = (float)j - C_HALF;

    // Sample coords in PADDED space (shift +1 for the border):
    //   sxp = co*x + si*y + (c+1)   (contiguous dim of g_P)
    //   syp = -si*x + co*y + (c+1)  (row dim of g_P)
    // If |si| > |co|, sample the transposed image with swapped roles so the
    // warp-contiguous spread stays in the contiguous memory dimension.
    const float bx = co * x + (C_HALF + 1.0f);
    const float by = -si * x + (C_HALF + 1.0f);

    const bool useT = fabsf(si) > fabsf(co);
    const float* __restrict__ P = useT ? g_PT : g_P;
    const float au = useT ? co : si;   // d(contig)/dy and base
    const float bu = useT ? by : bx;
    const float aw = useT ? si : co;   // d(row)/dy and base
    const float bw = useT ? bx : by;

    float acc = 0.0f;

    #pragma unroll 4
    for (int i = 0; i < N_IMG; ++i) {
        const float y = (float)i - C_HALF;
        const float u = fmaf(au, y, bu);   // contiguous (column) coordinate
        const float w = fmaf(aw, y, bw);   // row coordinate

        const float fu = floorf(u);
        const float fw = floorf(w);
        const float wu = u - fu;           // column fraction
        const float ww = w - fw;           // row fraction

        const int iu = (int)fu;
        const int iw = (int)fw;
        const int iu0 = clampi(iu,     0, PW - 1);
        const int iu1 = clampi(iu + 1, 0, PW - 1);
        const int iw0 = clampi(iw,     0, PW - 1);
        const int iw1 = clampi(iw + 1, 0, PW - 1);

        const float* r0 = P + iw0 * PW;
        const float* r1 = P + iw1 * PW;
        const float v00 = __ldg(r0 + iu0);
        const float v01 = __ldg(r0 + iu1);
        const float v10 = __ldg(r1 + iu0);
        const float v11 = __ldg(r1 + iu1);

        const float top = fmaf(v01 - v00, wu, v00);
        const float bot = fmaf(v11 - v10, wu, v10);
        acc += fmaf(bot - top, ww, top);
    }

    out[j * N_ANGLES + a] = acc;
}

extern "C" void kernel_launch(void* const* d_in, const int* in_sizes, int n_in,
                              void* d_out, int out_size) {
    const float* img    = (const float*)d_in[0];
    const int*   angles = (const int*)d_in[1];
    float*       out    = (float*)d_out;

    {
        int total = PW * PW;
        int threads = 256;
        int blocks = (total + threads - 1) / threads;
        prep_kernel<<<blocks, threads>>>(img);
    }
    {
        dim3 block(128, 1, 1);
        dim3 grid(N_IMG / 128, N_ANGLES, 1);
        radon_kernel<<<grid, block>>>(angles, out);
    }
}

// round 2
// speedup vs baseline: 1.7420x; 1.7420x over previous
#include <cuda_runtime.h>
#include <cuda_bf16.h>
#include <math.h>

#define N_IMG 512
#define N_ANGLES 180
#define C_HALF 255.5f

// Fully padded frame: sample coords span [255.5 - 361.34, 255.5 + 361.34]
// = [-105.9, 616.9]. Offset +106 -> floor indices in [0, 722], +1 tap <= 723.
#define W    728
#define OFF  106

// Pair images: Q[r*W+c] = (P(r,c), P(r,c+1)) so both column taps of the
// bilinear come from ONE LDG.64. QT is the transposed image (for steep angles).
__device__ float2 g_Q [W * W];
__device__ float2 g_QT[W * W];

__device__ __forceinline__ float img_at(const float* __restrict__ img, int r, int c) {
    // r,c in padded coords; zero outside the 512x512 image.
    int rr = r - OFF, cc = c - OFF;
    if (rr < 0 || rr >= N_IMG || cc < 0 || cc >= N_IMG) return 0.f;
    return img[rr * N_IMG + cc];
}

__global__ void prep_kernel(const float* __restrict__ img) {
    int idx = blockIdx.x * blockDim.x + threadIdx.x;
    if (idx >= W * W) return;
    int r = idx / W;
    int c = idx - r * W;
    float a  = img_at(img, r, c);
    float b  = (c + 1 < W) ? img_at(img, r, c + 1) : 0.f;
    float at = img_at(img, c, r);                         // transpose: swap roles
    float bt = (c + 1 < W) ? img_at(img, c + 1, r) : 0.f;
    g_Q [idx] = make_float2(a, b);
    g_QT[idx] = make_float2(at, bt);
}

// Block: 128 detectors (x) x 2 line-halves (y). Each thread integrates 256
// samples; halves combine via shared memory (2-term fp32 add -> deterministic).
__global__ void __launch_bounds__(256) radon_kernel(const int* __restrict__ angles,
                                                    float* __restrict__ out) {
    const int a  = blockIdx.y;
    const int tx = threadIdx.x;
    const int ty = threadIdx.y;
    const int j  = blockIdx.x * 128 + tx;

    const float t  = (float)angles[a] * (float)(3.14159265358979323846 / 180.0);
    const float co = cosf(t);
    const float si = sinf(t);
    const float x  = (float)j - C_HALF;

    // Padded-frame sample coords:
    //   u (contig) = co*x + si*y + (C + OFF)   [normal orientation]
    //   w (row)    = -si*x + co*y + (C + OFF)
    // Steep angles (|si|>|co|) sample the transposed image with roles swapped
    // so warp-contiguous detector spread stays in the contiguous dimension.
    const float bx = co * x + (C_HALF + (float)OFF);
    const float by = -si * x + (C_HALF + (float)OFF);

    const bool useT = fabsf(si) > fabsf(co);
    const float2* __restrict__ P = useT ? g_QT : g_Q;
    const float au = useT ? co : si;
    const float bu = useT ? by : bx;
    const float aw = useT ? si : co;
    const float bw = useT ? bx : by;

    const int i0 = ty * (N_IMG / 2);
    float acc = 0.0f;

    #pragma unroll 4
    for (int k = 0; k < N_IMG / 2; ++k) {
        const int   i = i0 + k;
        const float y = (float)i - C_HALF;
        const float u = fmaf(au, y, bu);   // contiguous coordinate (padded)
        const float w = fmaf(aw, y, bw);   // row coordinate (padded)

        const float fu = floorf(u);
        const float fw = floorf(w);
        const float wu = u - fu;
        const float ww = w - fw;

        const int iu = (int)fu;            // in [0, 722] by construction
        const int iw = (int)fw;

        const float2* row0 = P + iw * W + iu;
        const float2 v0 = __ldg(row0);         // (v00, v01)
        const float2 v1 = __ldg(row0 + W);     // (v10, v11)

        const float top = fmaf(v0.y - v0.x, wu, v0.x);
        const float bot = fmaf(v1.y - v1.x, wu, v1.x);
        acc += fmaf(bot - top, ww, top);
    }

    __shared__ float sh[128];
    if (ty == 1) sh[tx] = acc;
    __syncthreads();
    if (ty == 0) out[j * N_ANGLES + a] = acc + sh[tx];
}

extern "C" void kernel_launch(void* const* d_in, const int* in_sizes, int n_in,
                              void* d_out, int out_size) {
    const float* img    = (const float*)d_in[0];
    const int*   angles = (const int*)d_in[1];
    float*       out    = (float*)d_out;

    {
        int total = W * W;
        int threads = 256;
        int blocks = (total + threads - 1) / threads;
        prep_kernel<<<blocks, threads>>>(img);
    }
    {
        dim3 block(128, 2, 1);
        dim3 grid(N_IMG / 128, N_ANGLES, 1);
        radon_kernel<<<grid, block>>>(angles, out);
    }
}

// round 3
// speedup vs baseline: 2.2503x; 1.2918x over previous
#include <cuda_runtime.h>
#include <cuda_bf16.h>
#include <cuda_fp16.h>
#include <math.h>

#define N_IMG 512
#define N_ANGLES 180
#define C_HALF 255.5f

// Fully padded frame: sample coords span [255.5-361.34, 255.5+361.34]
// = [-105.9, 616.9]. Offset +106 -> floor indices in [0, 722], +1 tap <= 723.
#define W    728
#define OFF  106

// Quad-tap images: R4[r*W+c] = half4(P(r,c), P(r,c+1), P(r+1,c), P(r+1,c+1)).
// One 8-byte load yields all four bilinear taps. R4T is the transposed image
// (used for steep angles so warp-contiguous detector spread stays in the
// contiguous memory dimension).
__device__ ushort4 g_R4 [W * W];
__device__ ushort4 g_R4T[W * W];

__device__ __forceinline__ float img_at(const float* __restrict__ img, int r, int c) {
    int rr = r - OFF, cc = c - OFF;
    if (rr < 0 || rr >= N_IMG || cc < 0 || cc >= N_IMG) return 0.f;
    return img[rr * N_IMG + cc];
}

__global__ void prep_kernel(const float* __restrict__ img) {
    int idx = blockIdx.x * blockDim.x + threadIdx.x;
    if (idx >= W * W) return;
    int r = idx / W;
    int c = idx - r * W;

    // normal orientation
    float v00 = img_at(img, r,     c);
    float v01 = img_at(img, r,     c + 1);
    float v10 = img_at(img, r + 1, c);
    float v11 = img_at(img, r + 1, c + 1);
    ushort4 q;
    q.x = __half_as_ushort(__float2half_rn(v00));
    q.y = __half_as_ushort(__float2half_rn(v01));
    q.z = __half_as_ushort(__float2half_rn(v10));
    q.w = __half_as_ushort(__float2half_rn(v11));
    g_R4[idx] = q;

    // transposed orientation: PT(r,c) = P(c,r)
    float t00 = img_at(img, c,     r);
    float t01 = img_at(img, c + 1, r);
    float t10 = img_at(img, c,     r + 1);
    float t11 = img_at(img, c + 1, r + 1);
    ushort4 qt;
    qt.x = __half_as_ushort(__float2half_rn(t00));
    qt.y = __half_as_ushort(__float2half_rn(t01));
    qt.z = __half_as_ushort(__float2half_rn(t10));
    qt.w = __half_as_ushort(__float2half_rn(t11));
    g_R4T[idx] = qt;
}

// Block: 128 detectors (x) x 2 line-halves (y). Each thread integrates 256
// samples; halves combine via shared memory (2-term fp32 add -> deterministic).
__global__ void __launch_bounds__(256) radon_kernel(const int* __restrict__ angles,
                                                    float* __restrict__ out) {
    const int a  = blockIdx.y;
    const int tx = threadIdx.x;
    const int ty = threadIdx.y;
    const int j  = blockIdx.x * 128 + tx;

    const float t  = (float)angles[a] * (float)(3.14159265358979323846 / 180.0);
    const float co = cosf(t);
    const float si = sinf(t);
    const float x  = (float)j - C_HALF;

    const float bx = co * x + (C_HALF + (float)OFF);
    const float by = -si * x + (C_HALF + (float)OFF);

    const bool useT = fabsf(si) > fabsf(co);
    const ushort4* __restrict__ P = useT ? g_R4T : g_R4;
    const float au = useT ? co : si;   // d(contig)/di
    const float aw = useT ? si : co;   // d(row)/di
    // Fold the (i - C_HALF) shift into the base so the loop uses u = au*i + cu.
    const float cu = (useT ? by : bx) - au * C_HALF;
    const float cw = (useT ? bx : by) - aw * C_HALF;

    const int i0 = ty * (N_IMG / 2);
    float acc = 0.0f;

    #pragma unroll 8
    for (int k = 0; k < N_IMG / 2; ++k) {
        const int   i  = i0 + k;
        const float fi = (float)i;
        const float u  = fmaf(au, fi, cu);   // contiguous coordinate, >= 0
        const float w  = fmaf(aw, fi, cw);   // row coordinate, >= 0

        const int iu = (int)u;               // trunc == floor (u,w >= 0)
        const int iw = (int)w;
        const float wu = u - (float)iu;
        const float ww = w - (float)iw;

        const ushort4 q = __ldg(P + iw * W + iu);
        const float2 r0 = __half22float2(*(const __half2*)&q.x);  // (v00, v01)
        const float2 r1 = __half22float2(*(const __half2*)&q.z);  // (v10, v11)

        const float top = fmaf(r0.y - r0.x, wu, r0.x);
        const float bot = fmaf(r1.y - r1.x, wu, r1.x);
        acc += fmaf(bot - top, ww, top);
    }

    __shared__ float sh[128];
    if (ty == 1) sh[tx] = acc;
    __syncthreads();
    if (ty == 0) out[j * N_ANGLES + a] = acc + sh[tx];
}

extern "C" void kernel_launch(void* const* d_in, const int* in_sizes, int n_in,
                              void* d_out, int out_size) {
    const float* img    = (const float*)d_in[0];
    const int*   angles = (const int*)d_in[1];
    float*       out    = (float*)d_out;

    {
        int total = W * W;
        int threads = 256;
        int blocks = (total + threads - 1) / threads;
        prep_kernel<<<blocks, threads>>>(img);
    }
    {
        dim3 block(128, 2, 1);
        dim3 grid(N_IMG / 128, N_ANGLES, 1);
        radon_kernel<<<grid, block>>>(angles, out);
    }
}